// round 13
// baseline (speedup 1.0000x reference)
#include <cuda_runtime.h>
#include <cuda_fp16.h>
#include <cstdint>

#define N_NODES 100000
#define N_EDGES 1600000
#define D 128
#define CAP 64            // bin capacity per destination
#define GM 128            // nodes per GEMM CTA

// XOR-swizzled byte offset in a 128-row x 128-byte chunk buffer
#define SWZ(row, kb) ((row) * 128 + ((kb) ^ (((row) & 7) << 4)))

// ---- scratch (no allocations allowed) ----
__device__ __half g_msgh[N_NODES * D];     // agg, fp16
__device__ int    g_cnt[N_NODES];
__device__ int    g_bin[N_NODES * CAP];
__device__ __half g_wth[128 * 256];        // [Wl|Wr] fp16, [n][k]
__device__ __half g_xh[N_NODES * D];       // fp16 copy of x
__device__ int    g_is64;

__device__ __forceinline__ void mma_f16(float* c, const uint32_t* a,
                                        uint32_t b0, uint32_t b1) {
    asm volatile(
        "mma.sync.aligned.m16n8k16.row.col.f32.f16.f16.f32 "
        "{%0,%1,%2,%3}, {%4,%5,%6,%7}, {%8,%9}, {%0,%1,%2,%3};"
        : "+f"(c[0]), "+f"(c[1]), "+f"(c[2]), "+f"(c[3])
        : "r"(a[0]), "r"(a[1]), "r"(a[2]), "r"(a[3]), "r"(b0), "r"(b1));
}
__device__ __forceinline__ void ldsm4(uint32_t* r, uint32_t addr) {
    asm volatile("ldmatrix.sync.aligned.m8n8.x4.shared.b16 {%0,%1,%2,%3}, [%4];"
                 : "=r"(r[0]), "=r"(r[1]), "=r"(r[2]), "=r"(r[3]) : "r"(addr));
}
__device__ __forceinline__ uint32_t smem_u32(const void* p) {
    uint32_t a;
    asm("{ .reg .u64 t; cvta.to.shared.u64 t, %1; cvt.u32.u64 %0, t; }" : "=r"(a) : "l"(p));
    return a;
}
__device__ __forceinline__ void cpa16(uint32_t dst, const void* src) {
    asm volatile("cp.async.cg.shared.global [%0], [%1], 16;" :: "r"(dst), "l"(src));
}
#define CP_COMMIT() asm volatile("cp.async.commit_group;" ::: "memory")
#define CP_WAIT(n)  asm volatile("cp.async.wait_group %0;" :: "n"(n) : "memory")

// ============ prep: dtype detect + W->fp16 + cnt zero + x->fp16 =======
__global__ void prep_kernel(const float* __restrict__ Wl,
                            const float* __restrict__ Wr,
                            const float* __restrict__ x,
                            const long long* __restrict__ ei64,
                            __half2* __restrict__ wth2,
                            int* __restrict__ cnt,
                            uint2* __restrict__ xh4) {
    if (blockIdx.x == 0 && threadIdx.x < 32) {
        int lane = threadIdx.x;
        int bad = 0;
        for (int i = lane; i < 1024; i += 32) {
            long long v = ei64[i];
            if (v < 0 || v >= N_NODES) bad = 1;
        }
        unsigned m = __ballot_sync(0xFFFFFFFFu, bad);
        if (lane == 0) g_is64 = (m == 0u) ? 1 : 0;
    }
    int i = blockIdx.x * 256 + threadIdx.x;
    if (i < 128 * 128) {
        int n = i >> 7, k = (i & 127) * 2;
        float a, b;
        if (k < 128) { a = Wl[n * 128 + k];       b = Wl[n * 128 + k + 1]; }
        else         { a = Wr[n * 128 + k - 128]; b = Wr[n * 128 + k - 127]; }
        wth2[i] = __floats2half2_rn(a, b);
    }
    if (i < N_NODES) cnt[i] = 0;
    if (i < N_NODES * D / 4) {
        float4 v = ((const float4*)x)[i];
        __half2 h0 = __floats2half2_rn(v.x, v.y);
        __half2 h1 = __floats2half2_rn(v.z, v.w);
        uint2 st;
        st.x = *(const uint32_t*)&h0;
        st.y = *(const uint32_t*)&h1;
        xh4[i] = st;
    }
}

// ============================ bin edges by dst ========================
__global__ void bin_kernel(const float* __restrict__ x,
                           const void* __restrict__ ei_raw,
                           __half* __restrict__ msgh) {
    int base = blockIdx.x * blockDim.x + threadIdx.x;
    int stride = gridDim.x * blockDim.x;
#pragma unroll
    for (int q = 0; q < 4; q++) {
        int e = base + q * stride;
        if (e >= N_EDGES) break;
        int src, dst;
        if (g_is64) {
            const long long* ei = (const long long*)ei_raw;
            src = (int)ei[e]; dst = (int)ei[N_EDGES + e];
        } else {
            const int* ei = (const int*)ei_raw;
            src = ei[e]; dst = ei[N_EDGES + e];
        }
        if ((unsigned)src >= N_NODES || (unsigned)dst >= N_NODES) continue;
        int o = atomicAdd(&g_cnt[dst], 1);
        if (o < CAP) {
            g_bin[dst * CAP + o] = src;
        } else {
            // essentially-never fallback: atomic-add row into fp16 msg (zeroed)
            const float4* xr = (const float4*)(x + (size_t)src * D);
            __half2* mp = (__half2*)(msgh + (size_t)dst * D);
#pragma unroll
            for (int i = 0; i < 32; i++) {
                float4 v = xr[i];
                atomicAdd(mp + i * 2,     __floats2half2_rn(v.x, v.y));
                atomicAdd(mp + i * 2 + 1, __floats2half2_rn(v.z, v.w));
            }
        }
    }
}

// ============================ gather-aggregate ========================
// Warp per destination node; lane covers 8 B (uint2) of the 256 B row.
// Edges in batches of 8: all 8 LDG issued before any accumulate (MLP=8).
__global__ void gather_kernel(const __half* __restrict__ xh,
                              __half* __restrict__ msgh) {
    __shared__ int sidx[8][CAP];
    const int wbl = threadIdx.x >> 5;
    const int lane = threadIdx.x & 31;
    const int w = blockIdx.x * 8 + wbl;       // exact: grid = 12500

    const int deg = g_cnt[w];
    const int n = min(deg, CAP);
    const int* bp = g_bin + (size_t)w * CAP;
    if (lane < n) sidx[wbl][lane] = bp[lane];
    if (32 + lane < n) sidx[wbl][32 + lane] = bp[32 + lane];
    __syncwarp();

    const uint2* xb = (const uint2*)xh;       // 32 uint2 per row
    float acc[4] = {0.f, 0.f, 0.f, 0.f};

    for (int i = 0; i < n; i += 8) {
        uint2 p[8];
        const int m = n - i;
#pragma unroll
        for (int j = 0; j < 8; j++) {
            int e = (i + j < n) ? (i + j) : (n - 1);   // clamped: safe load
            int s = sidx[wbl][e];
            p[j] = __ldg(xb + (size_t)s * 32 + lane);
        }
#pragma unroll
        for (int j = 0; j < 8; j++) {
            if (j < m) {
                float2 f0 = __half22float2(*(const __half2*)&p[j].x);
                float2 f1 = __half22float2(*(const __half2*)&p[j].y);
                acc[0] += f0.x; acc[1] += f0.y; acc[2] += f1.x; acc[3] += f1.y;
            }
        }
    }

    if (deg > CAP) {             // merge never-path fallback deposits
        uint2 mm = __ldg((const uint2*)(msgh + (size_t)w * D) + lane);
        float2 f0 = __half22float2(*(const __half2*)&mm.x);
        float2 f1 = __half22float2(*(const __half2*)&mm.y);
        acc[0] += f0.x; acc[1] += f0.y; acc[2] += f1.x; acc[3] += f1.y;
    }
    float inv = 1.0f / fmaxf((float)deg, 1.0f);
    __half2 h0 = __floats2half2_rn(acc[0] * inv, acc[1] * inv);
    __half2 h1 = __floats2half2_rn(acc[2] * inv, acc[3] * inv);
    uint2 st;
    st.x = *(const uint32_t*)&h0;
    st.y = *(const uint32_t*)&h1;
    ((uint2*)(msgh + (size_t)w * D))[lane] = st;
}

// ============ fp16 mma GEMM: ldmatrix + XOR swizzle + cp.async ========
// B (weights) fully staged upfront (4 chunks, no reuse); A double-buffered
// with restage AFTER the leading barrier -> one __syncthreads per chunk.
__global__ __launch_bounds__(256, 2)
void gemm_kernel(const __half* __restrict__ xh,
                 const __half* __restrict__ wth,
                 const float* __restrict__ bias,
                 const __half* __restrict__ msgh,
                 float* __restrict__ out) {
    extern __shared__ char smc[];
    float* sBias = (float*)(smc + 98304);

    const int tid = threadIdx.x;
    const int wid = tid >> 5, lid = tid & 31;
    const int grp = lid >> 2, thr = lid & 3;
    const int wm = (wid & 3) * 32;
    const int wn = (wid >> 2) * 64;
    const int n0 = blockIdx.x * GM;

    const uint32_t sb = smem_u32(smc);
    const uint32_t uB[4] = { sb, sb + 16384, sb + 32768, sb + 49152 };
    const uint32_t uA[2] = { sb + 65536, sb + 81920 };

    auto stageB = [&](int c) {
#pragma unroll
        for (int i = 0; i < 4; i++) {
            int idx = tid + i * 256;
            int row = idx >> 3;
            int kb = (idx & 7) * 16;
            cpa16(uB[c] + SWZ(row, kb), wth + row * 256 + c * 64 + kb / 2);
        }
    };
    auto stageA = [&](int b, int c) {
#pragma unroll
        for (int i = 0; i < 4; i++) {
            int idx = tid + i * 256;
            int row = idx >> 3;
            int kb = (idx & 7) * 16;
            int g = min(n0 + row, N_NODES - 1);
            const __half* ap = (c < 2)
                ? msgh + (size_t)g * D + c * 64 + kb / 2
                : xh + (size_t)g * D + (c - 2) * 64 + kb / 2;
            cpa16(uA[b] + SWZ(row, kb), ap);
        }
    };

    // prologue: all of B + A chunk 0
    stageB(0); stageB(1); stageB(2); stageB(3);
    stageA(0, 0);
    CP_COMMIT();
    if (tid < 128) sBias[tid] = bias[tid];

    const int rowf = lid & 15;
    const int colf = (lid >> 4) * 16;

    float acc[2][8][4];
#pragma unroll
    for (int mt = 0; mt < 2; mt++)
#pragma unroll
        for (int nt = 0; nt < 8; nt++)
#pragma unroll
            for (int i = 0; i < 4; i++) acc[mt][nt][i] = 0.f;

    for (int c = 0; c < 4; c++) {
        CP_WAIT(0);                 // chunk-c data (and B on c=0) landed
        __syncthreads();            // publish; all warps done with prev A buf
        if (c < 3) { stageA((c + 1) & 1, c + 1); CP_COMMIT(); }

        const uint32_t A = uA[c & 1];
        const uint32_t B = uB[c];
#pragma unroll
        for (int ks = 0; ks < 4; ks++) {
            const int kbase = ks * 32;
            uint32_t af[2][4];
#pragma unroll
            for (int mt = 0; mt < 2; mt++) {
                int r = wm + mt * 16 + rowf;
                ldsm4(af[mt], A + SWZ(r, kbase + colf));
            }
            uint32_t bf[8][2];
#pragma unroll
            for (int p = 0; p < 4; p++) {
                uint32_t t[4];
                int r = wn + p * 16 + rowf;
                ldsm4(t, B + SWZ(r, kbase + colf));
                bf[2 * p][0] = t[0]; bf[2 * p][1] = t[2];
                bf[2 * p + 1][0] = t[1]; bf[2 * p + 1][1] = t[3];
            }
#pragma unroll
            for (int nt = 0; nt < 8; nt++) {
                mma_f16(acc[0][nt], af[0], bf[nt][0], bf[nt][1]);
                mma_f16(acc[1][nt], af[1], bf[nt][0], bf[nt][1]);
            }
        }
    }

    // epilogue: c0/c1 at (row grp, col 2thr), c2/c3 at row grp+8
#pragma unroll
    for (int mt = 0; mt < 2; mt++) {
        int rA = n0 + wm + mt * 16 + grp;
        int rB = rA + 8;
#pragma unroll
        for (int nt = 0; nt < 8; nt++) {
            int c = wn + nt * 8 + thr * 2;
            float b0 = sBias[c], b1 = sBias[c + 1];
            if (rA < N_NODES) {
                float2 r;
                r.x = fmaxf(acc[mt][nt][0] + b0, 0.f);
                r.y = fmaxf(acc[mt][nt][1] + b1, 0.f);
                *(float2*)(out + (size_t)rA * D + c) = r;
            }
            if (rB < N_NODES) {
                float2 r;
                r.x = fmaxf(acc[mt][nt][2] + b0, 0.f);
                r.y = fmaxf(acc[mt][nt][3] + b1, 0.f);
                *(float2*)(out + (size_t)rB * D + c) = r;
            }
        }
    }
}

// ============================ launch =================================
extern "C" void kernel_launch(void* const* d_in, const int* in_sizes, int n_in,
                              void* d_out, int out_size) {
    const float* x  = (const float*)d_in[0];
    const void*  ei = d_in[1];
    const float* Wl = (const float*)d_in[2];
    const float* bl = (const float*)d_in[3];
    const float* Wr = (const float*)d_in[4];
    float* out = (float*)d_out;

    __half *msgh, *wth, *xh; int* cnt;
    cudaGetSymbolAddress((void**)&msgh, g_msgh);
    cudaGetSymbolAddress((void**)&cnt, g_cnt);
    cudaGetSymbolAddress((void**)&wth, g_wth);
    cudaGetSymbolAddress((void**)&xh, g_xh);

    prep_kernel<<<(N_NODES * D / 4 + 255) / 256, 256>>>(
        Wl, Wr, x, (const long long*)ei, (__half2*)wth, cnt, (uint2*)xh);
    cudaMemsetAsync(msgh, 0, sizeof(__half) * (size_t)N_NODES * D);
    bin_kernel<<<(N_EDGES + 1023) / 1024, 256>>>(x, ei, msgh);
    gather_kernel<<<N_NODES / 8, 256>>>(xh, msgh);

    int smem = 98304 + 512;
    cudaFuncSetAttribute(gemm_kernel,
                         cudaFuncAttributeMaxDynamicSharedMemorySize, smem);
    int gblocks = (N_NODES + GM - 1) / GM;
    gemm_kernel<<<gblocks, 256, smem>>>(xh, wth, bl, msgh, out);
}

// round 14
// speedup vs baseline: 1.0937x; 1.0937x over previous
#include <cuda_runtime.h>
#include <cuda_fp16.h>
#include <cstdint>

#define N_NODES 100000
#define N_EDGES 1600000
#define D 128
#define CAP 64            // bin capacity per destination
#define GM 128            // nodes per GEMM CTA
#define OVF_MAX 4096      // overflow pair list capacity (never reached)

// XOR-swizzled byte offset in a 128-row x 128-byte chunk buffer
#define SWZ(row, kb) ((row) * 128 + ((kb) ^ (((row) & 7) << 4)))

// ---- scratch (no allocations allowed) ----
__device__ __half g_msgh[N_NODES * D];     // agg, fp16 (written by gather only)
__device__ int    g_cnt[N_NODES];
__device__ int    g_bin[N_NODES * CAP];
__device__ __half g_wth[128 * 256];        // [Wl|Wr] fp16, [n][k]
__device__ __half g_xh[N_NODES * D];       // fp16 copy of x
__device__ int    g_is64;
__device__ int    g_ovf_n;
__device__ int    g_ovf[OVF_MAX * 2];      // (src,dst) overflow pairs

__device__ __forceinline__ void mma_f16(float* c, const uint32_t* a,
                                        uint32_t b0, uint32_t b1) {
    asm volatile(
        "mma.sync.aligned.m16n8k16.row.col.f32.f16.f16.f32 "
        "{%0,%1,%2,%3}, {%4,%5,%6,%7}, {%8,%9}, {%0,%1,%2,%3};"
        : "+f"(c[0]), "+f"(c[1]), "+f"(c[2]), "+f"(c[3])
        : "r"(a[0]), "r"(a[1]), "r"(a[2]), "r"(a[3]), "r"(b0), "r"(b1));
}
__device__ __forceinline__ void ldsm4(uint32_t* r, uint32_t addr) {
    asm volatile("ldmatrix.sync.aligned.m8n8.x4.shared.b16 {%0,%1,%2,%3}, [%4];"
                 : "=r"(r[0]), "=r"(r[1]), "=r"(r[2]), "=r"(r[3]) : "r"(addr));
}
__device__ __forceinline__ uint32_t smem_u32(const void* p) {
    uint32_t a;
    asm("{ .reg .u64 t; cvta.to.shared.u64 t, %1; cvt.u32.u64 %0, t; }" : "=r"(a) : "l"(p));
    return a;
}
__device__ __forceinline__ void cpa16(uint32_t dst, const void* src) {
    asm volatile("cp.async.cg.shared.global [%0], [%1], 16;" :: "r"(dst), "l"(src));
}
#define CP_COMMIT() asm volatile("cp.async.commit_group;" ::: "memory")
#define CP_WAIT(n)  asm volatile("cp.async.wait_group %0;" :: "n"(n) : "memory")

// ============ prep: dtype detect + W->fp16 + cnt zero + x->fp16 =======
__global__ void prep_kernel(const float* __restrict__ Wl,
                            const float* __restrict__ Wr,
                            const float* __restrict__ x,
                            const long long* __restrict__ ei64,
                            __half2* __restrict__ wth2,
                            int* __restrict__ cnt,
                            uint2* __restrict__ xh4) {
    if (blockIdx.x == 0 && threadIdx.x < 32) {
        int lane = threadIdx.x;
        int bad = 0;
        for (int i = lane; i < 1024; i += 32) {
            long long v = ei64[i];
            if (v < 0 || v >= N_NODES) bad = 1;
        }
        unsigned m = __ballot_sync(0xFFFFFFFFu, bad);
        if (lane == 0) { g_is64 = (m == 0u) ? 1 : 0; g_ovf_n = 0; }
    }
    int i = blockIdx.x * 256 + threadIdx.x;
    if (i < 128 * 128) {
        int n = i >> 7, k = (i & 127) * 2;
        float a, b;
        if (k < 128) { a = Wl[n * 128 + k];       b = Wl[n * 128 + k + 1]; }
        else         { a = Wr[n * 128 + k - 128]; b = Wr[n * 128 + k - 127]; }
        wth2[i] = __floats2half2_rn(a, b);
    }
    if (i < N_NODES) cnt[i] = 0;
    if (i < N_NODES * D / 4) {
        float4 v = ((const float4*)x)[i];
        __half2 h0 = __floats2half2_rn(v.x, v.y);
        __half2 h1 = __floats2half2_rn(v.z, v.w);
        uint2 st;
        st.x = *(const uint32_t*)&h0;
        st.y = *(const uint32_t*)&h1;
        xh4[i] = st;
    }
}

// ============================ bin edges by dst ========================
// 4 edges per thread (grid-stride); overflow -> tiny (src,dst) pair list.
__global__ void bin_kernel(const void* __restrict__ ei_raw) {
    int base = blockIdx.x * blockDim.x + threadIdx.x;
    int stride = gridDim.x * blockDim.x;
#pragma unroll
    for (int q = 0; q < 4; q++) {
        int e = base + q * stride;
        if (e >= N_EDGES) break;
        int src, dst;
        if (g_is64) {
            const long long* ei = (const long long*)ei_raw;
            src = (int)ei[e]; dst = (int)ei[N_EDGES + e];
        } else {
            const int* ei = (const int*)ei_raw;
            src = ei[e]; dst = ei[N_EDGES + e];
        }
        if ((unsigned)src >= N_NODES || (unsigned)dst >= N_NODES) continue;
        int o = atomicAdd(&g_cnt[dst], 1);
        if (o < CAP) {
            g_bin[dst * CAP + o] = src;
        } else {
            int o2 = atomicAdd(&g_ovf_n, 1);   // essentially never
            if (o2 < OVF_MAX) {
                g_ovf[o2 * 2] = src;
                g_ovf[o2 * 2 + 1] = dst;
            }
        }
    }
}

// ============================ gather-aggregate ========================
// Half-warp per destination node (100000 = 16 * 6250, exact). Lane covers a
// 16 B chunk of the 256 B row via LDG.128; indices broadcast from smem.
__global__ void gather_kernel(const __half* __restrict__ xh,
                              __half* __restrict__ msgh) {
    __shared__ int sidx[16][CAP];
    const int hw = threadIdx.x >> 4;          // half-warp 0..15
    const int l = threadIdx.x & 15;
    const int w = blockIdx.x * 16 + hw;       // exact: grid = 6250

    const int deg = g_cnt[w];
    const int n = min(deg, CAP);
    const int* bp = g_bin + (size_t)w * CAP;
    for (int j = l; j < n; j += 16) sidx[hw][j] = bp[j];
    __syncwarp();

    float acc[8] = {0.f, 0.f, 0.f, 0.f, 0.f, 0.f, 0.f, 0.f};
#pragma unroll 4
    for (int i = 0; i < n; i++) {
        int s = sidx[hw][i];
        uint4 p = __ldg((const uint4*)(xh + (size_t)s * D) + l);
        float2 f0 = __half22float2(*(const __half2*)&p.x);
        float2 f1 = __half22float2(*(const __half2*)&p.y);
        float2 f2 = __half22float2(*(const __half2*)&p.z);
        float2 f3 = __half22float2(*(const __half2*)&p.w);
        acc[0] += f0.x; acc[1] += f0.y; acc[2] += f1.x; acc[3] += f1.y;
        acc[4] += f2.x; acc[5] += f2.y; acc[6] += f3.x; acc[7] += f3.y;
    }

    if (deg > CAP) {             // essentially-never: scan overflow pair list
        int m = min(g_ovf_n, OVF_MAX);
        for (int i = 0; i < m; i++) {
            if (g_ovf[i * 2 + 1] == w) {
                int s = g_ovf[i * 2];
                uint4 p = __ldg((const uint4*)(xh + (size_t)s * D) + l);
                float2 f0 = __half22float2(*(const __half2*)&p.x);
                float2 f1 = __half22float2(*(const __half2*)&p.y);
                float2 f2 = __half22float2(*(const __half2*)&p.z);
                float2 f3 = __half22float2(*(const __half2*)&p.w);
                acc[0] += f0.x; acc[1] += f0.y; acc[2] += f1.x; acc[3] += f1.y;
                acc[4] += f2.x; acc[5] += f2.y; acc[6] += f3.x; acc[7] += f3.y;
            }
        }
    }
    float inv = 1.0f / fmaxf((float)deg, 1.0f);
    __half2 h0 = __floats2half2_rn(acc[0] * inv, acc[1] * inv);
    __half2 h1 = __floats2half2_rn(acc[2] * inv, acc[3] * inv);
    __half2 h2 = __floats2half2_rn(acc[4] * inv, acc[5] * inv);
    __half2 h3 = __floats2half2_rn(acc[6] * inv, acc[7] * inv);
    uint4 st;
    st.x = *(const uint32_t*)&h0;
    st.y = *(const uint32_t*)&h1;
    st.z = *(const uint32_t*)&h2;
    st.w = *(const uint32_t*)&h3;
    ((uint4*)(msgh + (size_t)w * D))[l] = st;
}

// ============ fp16 mma GEMM: ldmatrix + XOR swizzle + cp.async ========
// out = relu( [agg | x] @ wt^T + b ); K = 4 chunks of 64 halves, B and A
// double-buffered (R12 configuration).
__global__ __launch_bounds__(256, 2)
void gemm_kernel(const __half* __restrict__ xh,
                 const __half* __restrict__ wth,
                 const float* __restrict__ bias,
                 const __half* __restrict__ msgh,
                 float* __restrict__ out) {
    extern __shared__ char smc[];
    float* sBias = (float*)(smc + 65536);

    const int tid = threadIdx.x;
    const int wid = tid >> 5, lid = tid & 31;
    const int grp = lid >> 2, thr = lid & 3;
    const int wm = (wid & 3) * 32;
    const int wn = (wid >> 2) * 64;
    const int n0 = blockIdx.x * GM;

    const uint32_t sb = smem_u32(smc);
    const uint32_t ub[2] = { sb,          sb + 16384 };   // B chunk buffers
    const uint32_t ua[2] = { sb + 32768,  sb + 49152 };   // A chunk buffers

    if (tid < 128) sBias[tid] = bias[tid];

    auto stage = [&](int b, int c) {
#pragma unroll
        for (int i = 0; i < 4; i++) {
            int idx = tid + i * 256;
            int row = idx >> 3;
            int kb = (idx & 7) * 16;
            cpa16(ub[b] + SWZ(row, kb), wth + row * 256 + c * 64 + kb / 2);
            int g = min(n0 + row, N_NODES - 1);
            const __half* ap = (c < 2)
                ? msgh + (size_t)g * D + c * 64 + kb / 2
                : xh + (size_t)g * D + (c - 2) * 64 + kb / 2;
            cpa16(ua[b] + SWZ(row, kb), ap);
        }
    };

    const int rowf = lid & 15;
    const int colf = (lid >> 4) * 16;

    float acc[2][8][4];
#pragma unroll
    for (int mt = 0; mt < 2; mt++)
#pragma unroll
        for (int nt = 0; nt < 8; nt++)
#pragma unroll
            for (int i = 0; i < 4; i++) acc[mt][nt][i] = 0.f;

    stage(0, 0); CP_COMMIT();

    for (int c = 0; c < 4; c++) {
        if (c < 3) { stage((c + 1) & 1, c + 1); CP_COMMIT(); CP_WAIT(1); }
        else       { CP_WAIT(0); }
        __syncthreads();

        const uint32_t A = ua[c & 1];
        const uint32_t B = ub[c & 1];
#pragma unroll
        for (int ks = 0; ks < 4; ks++) {
            const int kbase = ks * 32;
            uint32_t af[2][4];
#pragma unroll
            for (int mt = 0; mt < 2; mt++) {
                int r = wm + mt * 16 + rowf;
                ldsm4(af[mt], A + SWZ(r, kbase + colf));
            }
            uint32_t bf[8][2];
#pragma unroll
            for (int p = 0; p < 4; p++) {
                uint32_t t[4];
                int r = wn + p * 16 + rowf;
                ldsm4(t, B + SWZ(r, kbase + colf));
                bf[2 * p][0] = t[0]; bf[2 * p][1] = t[2];
                bf[2 * p + 1][0] = t[1]; bf[2 * p + 1][1] = t[3];
            }
#pragma unroll
            for (int nt = 0; nt < 8; nt++) {
                mma_f16(acc[0][nt], af[0], bf[nt][0], bf[nt][1]);
                mma_f16(acc[1][nt], af[1], bf[nt][0], bf[nt][1]);
            }
        }
        __syncthreads();
    }

    // epilogue: c0/c1 at (row grp, col 2thr), c2/c3 at row grp+8
#pragma unroll
    for (int mt = 0; mt < 2; mt++) {
        int rA = n0 + wm + mt * 16 + grp;
        int rB = rA + 8;
#pragma unroll
        for (int nt = 0; nt < 8; nt++) {
            int c = wn + nt * 8 + thr * 2;
            float b0 = sBias[c], b1 = sBias[c + 1];
            if (rA < N_NODES) {
                float2 r;
                r.x = fmaxf(acc[mt][nt][0] + b0, 0.f);
                r.y = fmaxf(acc[mt][nt][1] + b1, 0.f);
                *(float2*)(out + (size_t)rA * D + c) = r;
            }
            if (rB < N_NODES) {
                float2 r;
                r.x = fmaxf(acc[mt][nt][2] + b0, 0.f);
                r.y = fmaxf(acc[mt][nt][3] + b1, 0.f);
                *(float2*)(out + (size_t)rB * D + c) = r;
            }
        }
    }
}

// ============================ launch =================================
extern "C" void kernel_launch(void* const* d_in, const int* in_sizes, int n_in,
                              void* d_out, int out_size) {
    const float* x  = (const float*)d_in[0];
    const void*  ei = d_in[1];
    const float* Wl = (const float*)d_in[2];
    const float* bl = (const float*)d_in[3];
    const float* Wr = (const float*)d_in[4];
    float* out = (float*)d_out;

    __half *msgh, *wth, *xh; int* cnt;
    cudaGetSymbolAddress((void**)&msgh, g_msgh);
    cudaGetSymbolAddress((void**)&cnt, g_cnt);
    cudaGetSymbolAddress((void**)&wth, g_wth);
    cudaGetSymbolAddress((void**)&xh, g_xh);

    prep_kernel<<<(N_NODES * D / 4 + 255) / 256, 256>>>(
        Wl, Wr, x, (const long long*)ei, (__half2*)wth, cnt, (uint2*)xh);
    bin_kernel<<<(N_EDGES + 1023) / 1024, 256>>>(ei);
    gather_kernel<<<N_NODES / 16, 256>>>(xh, msgh);

    int smem = 65536 + 512;
    cudaFuncSetAttribute(gemm_kernel,
                         cudaFuncAttributeMaxDynamicSharedMemorySize, smem);
    int gblocks = (N_NODES + GM - 1) / GM;
    gemm_kernel<<<gblocks, 256, smem>>>(xh, wth, bl, msgh, out);
}

// round 15
// speedup vs baseline: 1.1046x; 1.0099x over previous
#include <cuda_runtime.h>
#include <cuda_fp16.h>
#include <cstdint>

#define N_NODES 100000
#define N_EDGES 1600000
#define D 128
#define CAP 64            // bin capacity per destination
#define GM 256            // nodes per GEMM CTA (2 x 128-row tiles)
#define OVF_MAX 4096      // overflow pair list capacity (never reached)

// XOR-swizzled byte offset in a 128-row x 128-byte chunk buffer
#define SWZ(row, kb) ((row) * 128 + ((kb) ^ (((row) & 7) << 4)))

// ---- scratch (no allocations allowed) ----
__device__ __half g_msgh[N_NODES * D];     // agg, fp16 (written by gather only)
__device__ int    g_cnt[N_NODES];
__device__ int    g_bin[N_NODES * CAP];
__device__ __half g_wth[128 * 256];        // [Wl|Wr] fp16, [n][k]
__device__ __half g_xh[N_NODES * D];       // fp16 copy of x
__device__ int    g_is64;
__device__ int    g_ovf_n;
__device__ int    g_ovf[OVF_MAX * 2];      // (src,dst) overflow pairs

__device__ __forceinline__ void mma_f16(float* c, const uint32_t* a,
                                        uint32_t b0, uint32_t b1) {
    asm volatile(
        "mma.sync.aligned.m16n8k16.row.col.f32.f16.f16.f32 "
        "{%0,%1,%2,%3}, {%4,%5,%6,%7}, {%8,%9}, {%0,%1,%2,%3};"
        : "+f"(c[0]), "+f"(c[1]), "+f"(c[2]), "+f"(c[3])
        : "r"(a[0]), "r"(a[1]), "r"(a[2]), "r"(a[3]), "r"(b0), "r"(b1));
}
__device__ __forceinline__ void ldsm4(uint32_t* r, uint32_t addr) {
    asm volatile("ldmatrix.sync.aligned.m8n8.x4.shared.b16 {%0,%1,%2,%3}, [%4];"
                 : "=r"(r[0]), "=r"(r[1]), "=r"(r[2]), "=r"(r[3]) : "r"(addr));
}
__device__ __forceinline__ uint32_t smem_u32(const void* p) {
    uint32_t a;
    asm("{ .reg .u64 t; cvta.to.shared.u64 t, %1; cvt.u32.u64 %0, t; }" : "=r"(a) : "l"(p));
    return a;
}
__device__ __forceinline__ void cpa16(uint32_t dst, const void* src) {
    asm volatile("cp.async.cg.shared.global [%0], [%1], 16;" :: "r"(dst), "l"(src));
}
#define CP_COMMIT() asm volatile("cp.async.commit_group;" ::: "memory")
#define CP_WAIT(n)  asm volatile("cp.async.wait_group %0;" :: "n"(n) : "memory")

// ============ prep: dtype detect + W->fp16 + cnt zero + x->fp16 =======
__global__ void prep_kernel(const float* __restrict__ Wl,
                            const float* __restrict__ Wr,
                            const float* __restrict__ x,
                            const long long* __restrict__ ei64,
                            __half2* __restrict__ wth2,
                            int* __restrict__ cnt,
                            uint2* __restrict__ xh4) {
    if (blockIdx.x == 0 && threadIdx.x < 32) {
        int lane = threadIdx.x;
        int bad = 0;
        for (int i = lane; i < 1024; i += 32) {
            long long v = ei64[i];
            if (v < 0 || v >= N_NODES) bad = 1;
        }
        unsigned m = __ballot_sync(0xFFFFFFFFu, bad);
        if (lane == 0) { g_is64 = (m == 0u) ? 1 : 0; g_ovf_n = 0; }
    }
    int i = blockIdx.x * 256 + threadIdx.x;
    if (i < 128 * 128) {
        int n = i >> 7, k = (i & 127) * 2;
        float a, b;
        if (k < 128) { a = Wl[n * 128 + k];       b = Wl[n * 128 + k + 1]; }
        else         { a = Wr[n * 128 + k - 128]; b = Wr[n * 128 + k - 127]; }
        wth2[i] = __floats2half2_rn(a, b);
    }
    if (i < N_NODES) cnt[i] = 0;
    if (i < N_NODES * D / 4) {
        float4 v = ((const float4*)x)[i];
        __half2 h0 = __floats2half2_rn(v.x, v.y);
        __half2 h1 = __floats2half2_rn(v.z, v.w);
        uint2 st;
        st.x = *(const uint32_t*)&h0;
        st.y = *(const uint32_t*)&h1;
        xh4[i] = st;
    }
}

// ============================ bin edges by dst ========================
__global__ void bin_kernel(const void* __restrict__ ei_raw) {
    int base = blockIdx.x * blockDim.x + threadIdx.x;
    int stride = gridDim.x * blockDim.x;
#pragma unroll
    for (int q = 0; q < 4; q++) {
        int e = base + q * stride;
        if (e >= N_EDGES) break;
        int src, dst;
        if (g_is64) {
            const long long* ei = (const long long*)ei_raw;
            src = (int)ei[e]; dst = (int)ei[N_EDGES + e];
        } else {
            const int* ei = (const int*)ei_raw;
            src = ei[e]; dst = ei[N_EDGES + e];
        }
        if ((unsigned)src >= N_NODES || (unsigned)dst >= N_NODES) continue;
        int o = atomicAdd(&g_cnt[dst], 1);
        if (o < CAP) {
            g_bin[dst * CAP + o] = src;
        } else {
            int o2 = atomicAdd(&g_ovf_n, 1);   // essentially never
            if (o2 < OVF_MAX) {
                g_ovf[o2 * 2] = src;
                g_ovf[o2 * 2 + 1] = dst;
            }
        }
    }
}

// ============================ gather-aggregate ========================
// Half-warp per destination node; lane covers 16 B via LDG.128. Edges in
// pairs: HADD2 pre-sum in fp16, one convert+fp32 accumulate per pair.
__global__ void gather_kernel(const __half* __restrict__ xh,
                              __half* __restrict__ msgh) {
    __shared__ int sidx[16][CAP];
    const int hw = threadIdx.x >> 4;          // half-warp 0..15
    const int l = threadIdx.x & 15;
    const int w = blockIdx.x * 16 + hw;       // exact: grid = 6250

    const int deg = g_cnt[w];
    const int n = min(deg, CAP);
    const int* bp = g_bin + (size_t)w * CAP;
    for (int j = l; j < n; j += 16) sidx[hw][j] = bp[j];
    __syncwarp();

    float acc[8] = {0.f, 0.f, 0.f, 0.f, 0.f, 0.f, 0.f, 0.f};
    int i = 0;
#pragma unroll 2
    for (; i + 2 <= n; i += 2) {
        int s0 = sidx[hw][i];
        int s1 = sidx[hw][i + 1];
        uint4 p0 = __ldg((const uint4*)(xh + (size_t)s0 * D) + l);
        uint4 p1 = __ldg((const uint4*)(xh + (size_t)s1 * D) + l);
        __half2 q0 = __hadd2(*(const __half2*)&p0.x, *(const __half2*)&p1.x);
        __half2 q1 = __hadd2(*(const __half2*)&p0.y, *(const __half2*)&p1.y);
        __half2 q2 = __hadd2(*(const __half2*)&p0.z, *(const __half2*)&p1.z);
        __half2 q3 = __hadd2(*(const __half2*)&p0.w, *(const __half2*)&p1.w);
        float2 f0 = __half22float2(q0);
        float2 f1 = __half22float2(q1);
        float2 f2 = __half22float2(q2);
        float2 f3 = __half22float2(q3);
        acc[0] += f0.x; acc[1] += f0.y; acc[2] += f1.x; acc[3] += f1.y;
        acc[4] += f2.x; acc[5] += f2.y; acc[6] += f3.x; acc[7] += f3.y;
    }
    if (i < n) {                              // odd tail
        int s = sidx[hw][i];
        uint4 p = __ldg((const uint4*)(xh + (size_t)s * D) + l);
        float2 f0 = __half22float2(*(const __half2*)&p.x);
        float2 f1 = __half22float2(*(const __half2*)&p.y);
        float2 f2 = __half22float2(*(const __half2*)&p.z);
        float2 f3 = __half22float2(*(const __half2*)&p.w);
        acc[0] += f0.x; acc[1] += f0.y; acc[2] += f1.x; acc[3] += f1.y;
        acc[4] += f2.x; acc[5] += f2.y; acc[6] += f3.x; acc[7] += f3.y;
    }

    if (deg > CAP) {             // essentially-never: scan overflow pair list
        int m = min(g_ovf_n, OVF_MAX);
        for (int t = 0; t < m; t++) {
            if (g_ovf[t * 2 + 1] == w) {
                int s = g_ovf[t * 2];
                uint4 p = __ldg((const uint4*)(xh + (size_t)s * D) + l);
                float2 f0 = __half22float2(*(const __half2*)&p.x);
                float2 f1 = __half22float2(*(const __half2*)&p.y);
                float2 f2 = __half22float2(*(const __half2*)&p.z);
                float2 f3 = __half22float2(*(const __half2*)&p.w);
                acc[0] += f0.x; acc[1] += f0.y; acc[2] += f1.x; acc[3] += f1.y;
                acc[4] += f2.x; acc[5] += f2.y; acc[6] += f3.x; acc[7] += f3.y;
            }
        }
    }
    float inv = 1.0f / fmaxf((float)deg, 1.0f);
    __half2 h0 = __floats2half2_rn(acc[0] * inv, acc[1] * inv);
    __half2 h1 = __floats2half2_rn(acc[2] * inv, acc[3] * inv);
    __half2 h2 = __floats2half2_rn(acc[4] * inv, acc[5] * inv);
    __half2 h3 = __floats2half2_rn(acc[6] * inv, acc[7] * inv);
    uint4 st;
    st.x = *(const uint32_t*)&h0;
    st.y = *(const uint32_t*)&h1;
    st.z = *(const uint32_t*)&h2;
    st.w = *(const uint32_t*)&h3;
    ((uint4*)(msgh + (size_t)w * D))[l] = st;
}

// ============ fp16 mma GEMM: 256 rows/CTA, B staged once ==============
// out = relu( [agg | x] @ wt^T + b ). 8 A-chunks (2 halves x 4 K-chunks),
// A double-buffered, single sync per chunk, epilogue per half.
__global__ __launch_bounds__(256, 2)
void gemm_kernel(const __half* __restrict__ xh,
                 const __half* __restrict__ wth,
                 const float* __restrict__ bias,
                 const __half* __restrict__ msgh,
                 float* __restrict__ out) {
    extern __shared__ char smc[];
    float* sBias = (float*)(smc + 98304);

    const int tid = threadIdx.x;
    const int wid = tid >> 5, lid = tid & 31;
    const int grp = lid >> 2, thr = lid & 3;
    const int wm = (wid & 3) * 32;
    const int wn = (wid >> 2) * 64;
    const int n0 = blockIdx.x * GM;

    const uint32_t sb = smem_u32(smc);
    const uint32_t uB[4] = { sb, sb + 16384, sb + 32768, sb + 49152 };
    const uint32_t uA[2] = { sb + 65536, sb + 81920 };

    auto stageB = [&](int c) {
#pragma unroll
        for (int i = 0; i < 4; i++) {
            int idx = tid + i * 256;
            int row = idx >> 3;
            int kb = (idx & 7) * 16;
            cpa16(uB[c] + SWZ(row, kb), wth + row * 256 + c * 64 + kb / 2);
        }
    };
    // global chunk cc: half = cc>>2, K-chunk = cc&3
    auto stageA = [&](int b, int cc) {
        int half = cc >> 2, c = cc & 3;
#pragma unroll
        for (int i = 0; i < 4; i++) {
            int idx = tid + i * 256;
            int row = idx >> 3;
            int kb = (idx & 7) * 16;
            int g = min(n0 + half * 128 + row, N_NODES - 1);
            const __half* ap = (c < 2)
                ? msgh + (size_t)g * D + c * 64 + kb / 2
                : xh + (size_t)g * D + (c - 2) * 64 + kb / 2;
            cpa16(uA[b] + SWZ(row, kb), ap);
        }
    };

    stageB(0); stageB(1); stageB(2); stageB(3);
    stageA(0, 0);
    CP_COMMIT();
    if (tid < 128) sBias[tid] = bias[tid];

    const int rowf = lid & 15;
    const int colf = (lid >> 4) * 16;

    float acc[2][8][4];
#pragma unroll
    for (int mt = 0; mt < 2; mt++)
#pragma unroll
        for (int nt = 0; nt < 8; nt++)
#pragma unroll
            for (int i = 0; i < 4; i++) acc[mt][nt][i] = 0.f;

    auto epilogue = [&](int half) {
#pragma unroll
        for (int mt = 0; mt < 2; mt++) {
            int rA = n0 + half * 128 + wm + mt * 16 + grp;
            int rB = rA + 8;
#pragma unroll
            for (int nt = 0; nt < 8; nt++) {
                int c = wn + nt * 8 + thr * 2;
                float b0 = sBias[c], b1 = sBias[c + 1];
                if (rA < N_NODES) {
                    float2 r;
                    r.x = fmaxf(acc[mt][nt][0] + b0, 0.f);
                    r.y = fmaxf(acc[mt][nt][1] + b1, 0.f);
                    *(float2*)(out + (size_t)rA * D + c) = r;
                }
                if (rB < N_NODES) {
                    float2 r;
                    r.x = fmaxf(acc[mt][nt][2] + b0, 0.f);
                    r.y = fmaxf(acc[mt][nt][3] + b1, 0.f);
                    *(float2*)(out + (size_t)rB * D + c) = r;
                }
                acc[mt][nt][0] = 0.f; acc[mt][nt][1] = 0.f;
                acc[mt][nt][2] = 0.f; acc[mt][nt][3] = 0.f;
            }
        }
    };

    for (int cc = 0; cc < 8; cc++) {
        CP_WAIT(0);
        __syncthreads();            // prev-chunk reads done; this chunk landed
        if (cc < 7) { stageA((cc + 1) & 1, cc + 1); CP_COMMIT(); }

        const uint32_t A = uA[cc & 1];
        const uint32_t B = uB[cc & 3];
#pragma unroll
        for (int ks = 0; ks < 4; ks++) {
            const int kbase = ks * 32;
            uint32_t af[2][4];
#pragma unroll
            for (int mt = 0; mt < 2; mt++) {
                int r = wm + mt * 16 + rowf;
                ldsm4(af[mt], A + SWZ(r, kbase + colf));
            }
            uint32_t bf[8][2];
#pragma unroll
            for (int p = 0; p < 4; p++) {
                uint32_t t[4];
                int r = wn + p * 16 + rowf;
                ldsm4(t, B + SWZ(r, kbase + colf));
                bf[2 * p][0] = t[0]; bf[2 * p][1] = t[2];
                bf[2 * p + 1][0] = t[1]; bf[2 * p + 1][1] = t[3];
            }
#pragma unroll
            for (int nt = 0; nt < 8; nt++) {
                mma_f16(acc[0][nt], af[0], bf[nt][0], bf[nt][1]);
                mma_f16(acc[1][nt], af[1], bf[nt][0], bf[nt][1]);
            }
        }
        if (cc == 3) epilogue(0);
        else if (cc == 7) epilogue(1);
    }
}

// ============================ launch =================================
extern "C" void kernel_launch(void* const* d_in, const int* in_sizes, int n_in,
                              void* d_out, int out_size) {
    const float* x  = (const float*)d_in[0];
    const void*  ei = d_in[1];
    const float* Wl = (const float*)d_in[2];
    const float* bl = (const float*)d_in[3];
    const float* Wr = (const float*)d_in[4];
    float* out = (float*)d_out;

    __half *msgh, *wth, *xh; int* cnt;
    cudaGetSymbolAddress((void**)&msgh, g_msgh);
    cudaGetSymbolAddress((void**)&cnt, g_cnt);
    cudaGetSymbolAddress((void**)&wth, g_wth);
    cudaGetSymbolAddress((void**)&xh, g_xh);

    prep_kernel<<<(N_NODES * D / 4 + 255) / 256, 256>>>(
        Wl, Wr, x, (const long long*)ei, (__half2*)wth, cnt, (uint2*)xh);
    bin_kernel<<<(N_EDGES + 1023) / 1024, 256>>>(ei);
    gather_kernel<<<N_NODES / 16, 256>>>(xh, msgh);

    int smem = 98304 + 512;
    cudaFuncSetAttribute(gemm_kernel,
                         cudaFuncAttributeMaxDynamicSharedMemorySize, smem);
    int gblocks = (N_NODES + GM - 1) / GM;
    gemm_kernel<<<gblocks, 256, smem>>>(xh, wth, bl, msgh, out);
}

// round 16
// speedup vs baseline: 1.1375x; 1.0298x over previous
#include <cuda_runtime.h>
#include <cuda_fp16.h>
#include <cstdint>

#define N_NODES 100000
#define N_EDGES 1600000
#define D 128
#define CAP 64            // bin capacity per destination
#define GM 128            // nodes per GEMM CTA
#define OVF_MAX 4096      // overflow pair list capacity (never reached)

// XOR-swizzled byte offset in a 128-row x 128-byte chunk buffer
#define SWZ(row, kb) ((row) * 128 + ((kb) ^ (((row) & 7) << 4)))

// ---- scratch (no allocations allowed) ----
__device__ __half g_msgh[N_NODES * D];     // agg, fp16 (written by gather only)
__device__ int    g_cnt[N_NODES];
__device__ int    g_bin[N_NODES * CAP];
__device__ __half g_wth[128 * 256];        // [Wl|Wr] fp16, [n][k]
__device__ __half g_xh[N_NODES * D];       // fp16 copy of x
__device__ int    g_is64;
__device__ int    g_ovf_n;
__device__ int    g_ovf[OVF_MAX * 2];      // (src,dst) overflow pairs

__device__ __forceinline__ void mma_f16(float* c, const uint32_t* a,
                                        uint32_t b0, uint32_t b1) {
    asm volatile(
        "mma.sync.aligned.m16n8k16.row.col.f32.f16.f16.f32 "
        "{%0,%1,%2,%3}, {%4,%5,%6,%7}, {%8,%9}, {%0,%1,%2,%3};"
        : "+f"(c[0]), "+f"(c[1]), "+f"(c[2]), "+f"(c[3])
        : "r"(a[0]), "r"(a[1]), "r"(a[2]), "r"(a[3]), "r"(b0), "r"(b1));
}
__device__ __forceinline__ void ldsm4(uint32_t* r, uint32_t addr) {
    asm volatile("ldmatrix.sync.aligned.m8n8.x4.shared.b16 {%0,%1,%2,%3}, [%4];"
                 : "=r"(r[0]), "=r"(r[1]), "=r"(r[2]), "=r"(r[3]) : "r"(addr));
}
__device__ __forceinline__ uint32_t smem_u32(const void* p) {
    uint32_t a;
    asm("{ .reg .u64 t; cvta.to.shared.u64 t, %1; cvt.u32.u64 %0, t; }" : "=r"(a) : "l"(p));
    return a;
}
__device__ __forceinline__ void cpa16(uint32_t dst, const void* src) {
    asm volatile("cp.async.cg.shared.global [%0], [%1], 16;" :: "r"(dst), "l"(src));
}
#define CP_COMMIT() asm volatile("cp.async.commit_group;" ::: "memory")
#define CP_WAIT(n)  asm volatile("cp.async.wait_group %0;" :: "n"(n) : "memory")

// ============ prep: dtype detect + W->fp16 + cnt zero + x->fp16 =======
__global__ void prep_kernel(const float* __restrict__ Wl,
                            const float* __restrict__ Wr,
                            const float* __restrict__ x,
                            const long long* __restrict__ ei64,
                            __half2* __restrict__ wth2,
                            int* __restrict__ cnt,
                            uint2* __restrict__ xh4) {
    if (blockIdx.x == 0 && threadIdx.x < 32) {
        int lane = threadIdx.x;
        int bad = 0;
        for (int i = lane; i < 1024; i += 32) {
            long long v = ei64[i];
            if (v < 0 || v >= N_NODES) bad = 1;
        }
        unsigned m = __ballot_sync(0xFFFFFFFFu, bad);
        if (lane == 0) { g_is64 = (m == 0u) ? 1 : 0; g_ovf_n = 0; }
    }
    int i = blockIdx.x * 256 + threadIdx.x;
    if (i < 128 * 128) {
        int n = i >> 7, k = (i & 127) * 2;
        float a, b;
        if (k < 128) { a = Wl[n * 128 + k];       b = Wl[n * 128 + k + 1]; }
        else         { a = Wr[n * 128 + k - 128]; b = Wr[n * 128 + k - 127]; }
        wth2[i] = __floats2half2_rn(a, b);
    }
    if (i < N_NODES) cnt[i] = 0;
    if (i < N_NODES * D / 4) {
        float4 v = ((const float4*)x)[i];
        __half2 h0 = __floats2half2_rn(v.x, v.y);
        __half2 h1 = __floats2half2_rn(v.z, v.w);
        uint2 st;
        st.x = *(const uint32_t*)&h0;
        st.y = *(const uint32_t*)&h1;
        xh4[i] = st;
    }
}

// ============================ bin edges by dst ========================
__global__ void bin_kernel(const void* __restrict__ ei_raw) {
    int base = blockIdx.x * blockDim.x + threadIdx.x;
    int stride = gridDim.x * blockDim.x;
#pragma unroll
    for (int q = 0; q < 4; q++) {
        int e = base + q * stride;
        if (e >= N_EDGES) break;
        int src, dst;
        if (g_is64) {
            const long long* ei = (const long long*)ei_raw;
            src = (int)ei[e]; dst = (int)ei[N_EDGES + e];
        } else {
            const int* ei = (const int*)ei_raw;
            src = ei[e]; dst = ei[N_EDGES + e];
        }
        if ((unsigned)src >= N_NODES || (unsigned)dst >= N_NODES) continue;
        int o = atomicAdd(&g_cnt[dst], 1);
        if (o < CAP) {
            g_bin[dst * CAP + o] = src;
        } else {
            int o2 = atomicAdd(&g_ovf_n, 1);   // essentially never
            if (o2 < OVF_MAX) {
                g_ovf[o2 * 2] = src;
                g_ovf[o2 * 2 + 1] = dst;
            }
        }
    }
}

// ============================ gather-aggregate ========================
// Half-warp per destination node; lane covers 16 B via LDG.128. Edges in
// pairs: HADD2 pre-sum in fp16, one convert+fp32 accumulate per pair.
__global__ void gather_kernel(const __half* __restrict__ xh,
                              __half* __restrict__ msgh) {
    __shared__ int sidx[16][CAP];
    const int hw = threadIdx.x >> 4;          // half-warp 0..15
    const int l = threadIdx.x & 15;
    const int w = blockIdx.x * 16 + hw;       // exact: grid = 6250

    const int deg = g_cnt[w];
    const int n = min(deg, CAP);
    const int* bp = g_bin + (size_t)w * CAP;
    for (int j = l; j < n; j += 16) sidx[hw][j] = bp[j];
    __syncwarp();

    float acc[8] = {0.f, 0.f, 0.f, 0.f, 0.f, 0.f, 0.f, 0.f};
    int i = 0;
#pragma unroll 2
    for (; i + 2 <= n; i += 2) {
        int s0 = sidx[hw][i];
        int s1 = sidx[hw][i + 1];
        uint4 p0 = __ldg((const uint4*)(xh + (size_t)s0 * D) + l);
        uint4 p1 = __ldg((const uint4*)(xh + (size_t)s1 * D) + l);
        __half2 q0 = __hadd2(*(const __half2*)&p0.x, *(const __half2*)&p1.x);
        __half2 q1 = __hadd2(*(const __half2*)&p0.y, *(const __half2*)&p1.y);
        __half2 q2 = __hadd2(*(const __half2*)&p0.z, *(const __half2*)&p1.z);
        __half2 q3 = __hadd2(*(const __half2*)&p0.w, *(const __half2*)&p1.w);
        float2 f0 = __half22float2(q0);
        float2 f1 = __half22float2(q1);
        float2 f2 = __half22float2(q2);
        float2 f3 = __half22float2(q3);
        acc[0] += f0.x; acc[1] += f0.y; acc[2] += f1.x; acc[3] += f1.y;
        acc[4] += f2.x; acc[5] += f2.y; acc[6] += f3.x; acc[7] += f3.y;
    }
    if (i < n) {                              // odd tail
        int s = sidx[hw][i];
        uint4 p = __ldg((const uint4*)(xh + (size_t)s * D) + l);
        float2 f0 = __half22float2(*(const __half2*)&p.x);
        float2 f1 = __half22float2(*(const __half2*)&p.y);
        float2 f2 = __half22float2(*(const __half2*)&p.z);
        float2 f3 = __half22float2(*(const __half2*)&p.w);
        acc[0] += f0.x; acc[1] += f0.y; acc[2] += f1.x; acc[3] += f1.y;
        acc[4] += f2.x; acc[5] += f2.y; acc[6] += f3.x; acc[7] += f3.y;
    }

    if (deg > CAP) {             // essentially-never: scan overflow pair list
        int m = min(g_ovf_n, OVF_MAX);
        for (int t = 0; t < m; t++) {
            if (g_ovf[t * 2 + 1] == w) {
                int s = g_ovf[t * 2];
                uint4 p = __ldg((const uint4*)(xh + (size_t)s * D) + l);
                float2 f0 = __half22float2(*(const __half2*)&p.x);
                float2 f1 = __half22float2(*(const __half2*)&p.y);
                float2 f2 = __half22float2(*(const __half2*)&p.z);
                float2 f3 = __half22float2(*(const __half2*)&p.w);
                acc[0] += f0.x; acc[1] += f0.y; acc[2] += f1.x; acc[3] += f1.y;
                acc[4] += f2.x; acc[5] += f2.y; acc[6] += f3.x; acc[7] += f3.y;
            }
        }
    }
    float inv = 1.0f / fmaxf((float)deg, 1.0f);
    __half2 h0 = __floats2half2_rn(acc[0] * inv, acc[1] * inv);
    __half2 h1 = __floats2half2_rn(acc[2] * inv, acc[3] * inv);
    __half2 h2 = __floats2half2_rn(acc[4] * inv, acc[5] * inv);
    __half2 h3 = __floats2half2_rn(acc[6] * inv, acc[7] * inv);
    uint4 st;
    st.x = *(const uint32_t*)&h0;
    st.y = *(const uint32_t*)&h1;
    st.z = *(const uint32_t*)&h2;
    st.w = *(const uint32_t*)&h3;
    ((uint4*)(msgh + (size_t)w * D))[l] = st;
}

// ============ fp16 mma GEMM: ldmatrix + XOR swizzle + cp.async ========
// R12/R14 configuration: GM=128, B and A double-buffered, 2 CTAs/SM.
__global__ __launch_bounds__(256, 2)
void gemm_kernel(const __half* __restrict__ xh,
                 const __half* __restrict__ wth,
                 const float* __restrict__ bias,
                 const __half* __restrict__ msgh,
                 float* __restrict__ out) {
    extern __shared__ char smc[];
    float* sBias = (float*)(smc + 65536);

    const int tid = threadIdx.x;
    const int wid = tid >> 5, lid = tid & 31;
    const int grp = lid >> 2, thr = lid & 3;
    const int wm = (wid & 3) * 32;
    const int wn = (wid >> 2) * 64;
    const int n0 = blockIdx.x * GM;

    const uint32_t sb = smem_u32(smc);
    const uint32_t ub[2] = { sb,          sb + 16384 };   // B chunk buffers
    const uint32_t ua[2] = { sb + 32768,  sb + 49152 };   // A chunk buffers

    if (tid < 128) sBias[tid] = bias[tid];

    auto stage = [&](int b, int c) {
#pragma unroll
        for (int i = 0; i < 4; i++) {
            int idx = tid + i * 256;
            int row = idx >> 3;
            int kb = (idx & 7) * 16;
            cpa16(ub[b] + SWZ(row, kb), wth + row * 256 + c * 64 + kb / 2);
            int g = min(n0 + row, N_NODES - 1);
            const __half* ap = (c < 2)
                ? msgh + (size_t)g * D + c * 64 + kb / 2
                : xh + (size_t)g * D + (c - 2) * 64 + kb / 2;
            cpa16(ua[b] + SWZ(row, kb), ap);
        }
    };

    const int rowf = lid & 15;
    const int colf = (lid >> 4) * 16;

    float acc[2][8][4];
#pragma unroll
    for (int mt = 0; mt < 2; mt++)
#pragma unroll
        for (int nt = 0; nt < 8; nt++)
#pragma unroll
            for (int i = 0; i < 4; i++) acc[mt][nt][i] = 0.f;

    stage(0, 0); CP_COMMIT();

    for (int c = 0; c < 4; c++) {
        if (c < 3) { stage((c + 1) & 1, c + 1); CP_COMMIT(); CP_WAIT(1); }
        else       { CP_WAIT(0); }
        __syncthreads();

        const uint32_t A = ua[c & 1];
        const uint32_t B = ub[c & 1];
#pragma unroll
        for (int ks = 0; ks < 4; ks++) {
            const int kbase = ks * 32;
            uint32_t af[2][4];
#pragma unroll
            for (int mt = 0; mt < 2; mt++) {
                int r = wm + mt * 16 + rowf;
                ldsm4(af[mt], A + SWZ(r, kbase + colf));
            }
            uint32_t bf[8][2];
#pragma unroll
            for (int p = 0; p < 4; p++) {
                uint32_t t[4];
                int r = wn + p * 16 + rowf;
                ldsm4(t, B + SWZ(r, kbase + colf));
                bf[2 * p][0] = t[0]; bf[2 * p][1] = t[2];
                bf[2 * p + 1][0] = t[1]; bf[2 * p + 1][1] = t[3];
            }
#pragma unroll
            for (int nt = 0; nt < 8; nt++) {
                mma_f16(acc[0][nt], af[0], bf[nt][0], bf[nt][1]);
                mma_f16(acc[1][nt], af[1], bf[nt][0], bf[nt][1]);
            }
        }
        __syncthreads();
    }

    // epilogue: c0/c1 at (row grp, col 2thr), c2/c3 at row grp+8
#pragma unroll
    for (int mt = 0; mt < 2; mt++) {
        int rA = n0 + wm + mt * 16 + grp;
        int rB = rA + 8;
#pragma unroll
        for (int nt = 0; nt < 8; nt++) {
            int c = wn + nt * 8 + thr * 2;
            float b0 = sBias[c], b1 = sBias[c + 1];
            if (rA < N_NODES) {
                float2 r;
                r.x = fmaxf(acc[mt][nt][0] + b0, 0.f);
                r.y = fmaxf(acc[mt][nt][1] + b1, 0.f);
                *(float2*)(out + (size_t)rA * D + c) = r;
            }
            if (rB < N_NODES) {
                float2 r;
                r.x = fmaxf(acc[mt][nt][2] + b0, 0.f);
                r.y = fmaxf(acc[mt][nt][3] + b1, 0.f);
                *(float2*)(out + (size_t)rB * D + c) = r;
            }
        }
    }
}

// ============================ launch =================================
extern "C" void kernel_launch(void* const* d_in, const int* in_sizes, int n_in,
                              void* d_out, int out_size) {
    const float* x  = (const float*)d_in[0];
    const void*  ei = d_in[1];
    const float* Wl = (const float*)d_in[2];
    const float* bl = (const float*)d_in[3];
    const float* Wr = (const float*)d_in[4];
    float* out = (float*)d_out;

    __half *msgh, *wth, *xh; int* cnt;
    cudaGetSymbolAddress((void**)&msgh, g_msgh);
    cudaGetSymbolAddress((void**)&cnt, g_cnt);
    cudaGetSymbolAddress((void**)&wth, g_wth);
    cudaGetSymbolAddress((void**)&xh, g_xh);

    prep_kernel<<<(N_NODES * D / 4 + 255) / 256, 256>>>(
        Wl, Wr, x, (const long long*)ei, (__half2*)wth, cnt, (uint2*)xh);
    bin_kernel<<<(N_EDGES + 1023) / 1024, 256>>>(ei);
    gather_kernel<<<N_NODES / 16, 256>>>(xh, msgh);

    int smem = 65536 + 512;
    cudaFuncSetAttribute(gemm_kernel,
                         cudaFuncAttributeMaxDynamicSharedMemorySize, smem);
    int gblocks = (N_NODES + GM - 1) / GM;
    gemm_kernel<<<gblocks, 256, smem>>>(xh, wth, bl, msgh, out);
}